// round 12
// baseline (speedup 1.0000x reference)
#include <cuda_runtime.h>
#include <cuda_fp16.h>
#include <stdint.h>

#define BB 8
#define NN 2048
#define DD 256
#define BN (BB * NN)
#define TM 32
#define NCH_H 32          // chunks per half (m-split x2)

// ---------------- device scratch (allocation-free) ----------------
__device__ __half g_xhi[BN * DD];        // X row-major fp16
__device__ __half g_xthi[BB * DD * NN];  // X^T [b][k][m] fp16 (V side)
__device__ __half g_wthi[DD * DD];       // W^T [n][k] fp16
__device__ float g_part[2 * BN * DD];    // partial numerators (per m-half)
__device__ float g_den[2 * BN];          // partial denominators (scaled)
__device__ float g_sh2[BN];              // per-row exponent shift (log2 units)

// ---------------- helpers ----------------
__device__ __forceinline__ uint32_t smem_u32(const void* p) {
    uint32_t a;
    asm("{ .reg .u64 t; cvta.to.shared.u64 t, %1; cvt.u32.u64 %0, t; }" : "=r"(a) : "l"(p));
    return a;
}
__device__ __forceinline__ void ldsm4(uint32_t* r, uint32_t a) {
    asm volatile("ldmatrix.sync.aligned.m8n8.x4.shared.b16 {%0,%1,%2,%3}, [%4];"
                 : "=r"(r[0]), "=r"(r[1]), "=r"(r[2]), "=r"(r[3]) : "r"(a));
}
__device__ __forceinline__ void mma16816(float* c, const uint32_t* a, const uint32_t* b) {
    asm volatile("mma.sync.aligned.m16n8k16.row.col.f32.f16.f16.f32 "
                 "{%0,%1,%2,%3},{%4,%5,%6,%7},{%8,%9},{%0,%1,%2,%3};"
                 : "+f"(c[0]), "+f"(c[1]), "+f"(c[2]), "+f"(c[3])
                 : "r"(a[0]), "r"(a[1]), "r"(a[2]), "r"(a[3]), "r"(b[0]), "r"(b[1]));
}
#define CPA16(dst, src) \
    asm volatile("cp.async.cg.shared.global [%0], [%1], 16;" :: "r"(dst), "l"(src))
#define CP_COMMIT() asm volatile("cp.async.commit_group;")
#define CP_WAIT(n)  asm volatile("cp.async.wait_group %0;" :: "n"(n))
#define BAR_PAIR(id) asm volatile("bar.sync %0, 64;" :: "r"(id) : "memory")

// pack two f32 -> f16x2 (lo arg -> low half)
__device__ __forceinline__ uint32_t cvt2h(float lo, float hi) {
    uint32_t r;
    asm("cvt.rn.f16x2.f32 %0, %1, %2;" : "=r"(r) : "f"(hi), "f"(lo));
    return r;
}
__device__ __forceinline__ float2 h2f2(uint32_t u) {
    __half2 h = *(__half2*)&u;
    return __half22float2(h);
}
// p' = exp2(s*log2(e)/16 - sh)
__device__ __forceinline__ float fexp16s(float s, float sh) {
    float r;
    asm("ex2.approx.f32 %0, %1;" : "=f"(r) : "f"(fmaf(s, 0.09016844005556021f, -sh)));
    return r;
}

// ---------------- preprocessing ----------------
__global__ void __launch_bounds__(256) norm_kernel(const float* __restrict__ inp) {
    const int row = blockIdx.x * 8 + (threadIdx.x >> 5);
    const int lane = threadIdx.x & 31;
    const float4* p = (const float4*)(inp + (size_t)row * DD);
    const float4 a = p[lane];
    const float4 b = p[lane + 32];
    float s = a.x * a.x + a.y * a.y + a.z * a.z + a.w * a.w +
              b.x * b.x + b.y * b.y + b.z * b.z + b.w * b.w;
#pragma unroll
    for (int o = 16; o > 0; o >>= 1) s += __shfl_xor_sync(0xFFFFFFFFu, s, o);
    if (lane == 0)
        g_sh2[row] = (s * 0.0625f - 8.0f) * 1.44269504f;
}

__global__ void __launch_bounds__(256) split_x_kernel(const float* __restrict__ inp) {
    __shared__ float t[32][33];
    const int b = blockIdx.z;
    const int m0 = blockIdx.x * 32, k0 = blockIdx.y * 32;
    const int tx = threadIdx.x, ty = threadIdx.y;
    const float* src = inp + ((size_t)b * NN + m0) * DD + k0;
#pragma unroll
    for (int s = 0; s < 4; s++) {
        const int m = ty + 8 * s;
        const float v = src[(size_t)m * DD + tx];
        t[m][tx] = v;
        g_xhi[((size_t)b * NN + m0 + m) * DD + k0 + tx] = __float2half_rn(v);
    }
    __syncthreads();
#pragma unroll
    for (int s = 0; s < 4; s++) {
        const int c = ty + 8 * s;
        g_xthi[((size_t)b * DD + k0 + c) * NN + m0 + tx] = __float2half_rn(t[tx][c]);
    }
}

__global__ void __launch_bounds__(256) split_wt_kernel(const float* __restrict__ W) {
    __shared__ float t[32][33];
    const int k0 = blockIdx.x * 32, n0 = blockIdx.y * 32;
    const int tx = threadIdx.x, ty = threadIdx.y;
#pragma unroll
    for (int s = 0; s < 4; s++) t[ty + 8 * s][tx] = W[(size_t)(k0 + ty + 8 * s) * DD + n0 + tx];
    __syncthreads();
#pragma unroll
    for (int s = 0; s < 4; s++) {
        const int k = ty + 8 * s;
        g_wthi[(size_t)(n0 + tx) * DD + k0 + k] = __float2half_rn(t[k][tx]);
    }
}

// ---------------- fused attention (TM=32, 2 CTAs/SM, pair barriers) ----------------
#define S_QHI 0u
#define S_K0  33792u
#define S_K1  50688u
#define S_V0  67584u
#define S_V1  88064u
#define S_PHI 108544u
#define S_DEN 113664u
#define SMEM_ATTN 114176u

__global__ void __launch_bounds__(256, 2) attn_kernel(const float* __restrict__ adj) {
    extern __shared__ char smem[];
    const uint32_t sb = smem_u32(smem);
    const int tid = threadIdx.x;
    const int wid = tid >> 5, lane = tid & 31;
    const int s = wid >> 1, hs = wid & 1;
    const int lane7 = lane & 7, l34 = (lane >> 3) & 1, l4 = lane >> 4;

    const int bb = blockIdx.x >> 6;
    const int i0 = ((blockIdx.x >> 1) & 31) * 64;
    const int half = blockIdx.x & 1;
    const int mbase = half * (NCH_H * TM);

    const __half* __restrict__ xhiB = g_xhi + (size_t)bb * NN * DD;
    const __half* __restrict__ xthiB = g_xthi + (size_t)bb * DD * NN;
    const float* __restrict__ adjB = adj + (size_t)bb * NN * NN;

    float* den_sm = (float*)(smem + S_DEN);  // [2][64]
    if (tid < 128) den_sm[tid] = 0.f;

    const int ldRowK = tid >> 5, ldC16K = tid & 31;   // K: 32 rows x 32 chunks
    const int ldRowV = tid >> 2, ldC16V = tid & 3;    // V: 256 rows x 4 chunks

    // ---- G0: Q + K(0)->K0 + V(0)->V0 ----
#pragma unroll
    for (int it = 0; it < 8; it++) {
        const int row = ldRowK + it * 8;
        CPA16(sb + S_QHI + row * 528 + ldC16K * 16, xhiB + (size_t)(i0 + row) * DD + ldC16K * 8);
    }
#pragma unroll
    for (int it = 0; it < 4; it++) {
        const int row = ldRowK + it * 8;
        CPA16(sb + S_K0 + row * 528 + ldC16K * 16, xhiB + (size_t)(mbase + row) * DD + ldC16K * 8);
    }
#pragma unroll
    for (int it = 0; it < 4; it++) {
        const int row = ldRowV + it * 64;
        CPA16(sb + S_V0 + row * 80 + ldC16V * 16, xthiB + (size_t)row * NN + mbase + ldC16V * 8);
    }
    CP_COMMIT();
    // ---- G1: K(1)->K1 + V(1)->V1 ----
#pragma unroll
    for (int it = 0; it < 4; it++) {
        const int row = ldRowK + it * 8;
        CPA16(sb + S_K1 + row * 528 + ldC16K * 16, xhiB + (size_t)(mbase + TM + row) * DD + ldC16K * 8);
    }
#pragma unroll
    for (int it = 0; it < 4; it++) {
        const int row = ldRowV + it * 64;
        CPA16(sb + S_V1 + row * 80 + ldC16V * 16, xthiB + (size_t)row * NN + mbase + TM + ldC16V * 8);
    }
    CP_COMMIT();

    // fragment addresses
    const int aRow = s * 16 + lane7 + l34 * 8;
    const uint32_t aQhi = sb + S_QHI + aRow * 528 + l4 * 16;
    const int bRowS = hs * 16 + l4 * 8 + lane7;
    const uint32_t kFrag = (uint32_t)(bRowS * 528 + l34 * 16);
    const uint32_t aPhi = sb + S_PHI + aRow * 80 + l4 * 16;
    const int vRow = hs * 128 + l4 * 8 + lane7;
    const uint32_t vFrag = (uint32_t)(vRow * 80 + l34 * 16);
    const uint32_t kBuf[2] = {sb + S_K0, sb + S_K1};
    const uint32_t vBuf[2] = {sb + S_V0, sb + S_V1};

    const int r0 = s * 16 + (lane >> 2);
    const int cb = hs * 16 + (lane & 3) * 2;
    const uint32_t psHi0 = sb + S_PHI + r0 * 80 + cb * 2;

    // per-row exponent shifts
    const float sh0 = g_sh2[(size_t)bb * NN + i0 + r0];
    const float sh1 = g_sh2[(size_t)bb * NN + i0 + r0 + 8];

    float oacc[16][4];
#pragma unroll
    for (int i = 0; i < 16; i++)
#pragma unroll
        for (int j = 0; j < 4; j++) oacc[i][j] = 0.f;
    float den0 = 0.f, den1 = 0.f;

    for (int ch = 0; ch < NCH_H; ch++) {
        const int m0 = mbase + ch * TM;
        const int cur = ch & 1;
        CP_WAIT(1);          // K(ch),V(ch) ready
        __syncthreads();     // sync1: buffers safe to read; prev P consumed

        // adj prefetch (hidden under S MMAs)
        const float* adjR0 = adjB + (size_t)(i0 + r0) * NN + m0 + cb;
        const float* adjR1 = adjR0 + 8 * NN;
        float2 aj0[2], aj1[2];
#pragma unroll
        for (int nt = 0; nt < 2; nt++) {
            aj0[nt] = __ldg((const float2*)(adjR0 + nt * 8));
            aj1[nt] = __ldg((const float2*)(adjR1 + nt * 8));
        }

        // ---- S = Qh * Kh  (warp: 16 rows x 16 cols) ----
        const uint32_t kB = kBuf[cur] + kFrag;
        float sacc[2][4];
#pragma unroll
        for (int i = 0; i < 2; i++)
#pragma unroll
            for (int j = 0; j < 4; j++) sacc[i][j] = 0.f;

#pragma unroll
        for (int kk = 0; kk < 16; kk++) {
            const uint32_t ko = kk * 32;
            uint32_t ah[4], b0[4];
            ldsm4(ah, aQhi + ko);
            ldsm4(b0, kB + ko);
            mma16816(sacc[0], ah, b0 + 0);
            mma16816(sacc[1], ah, b0 + 2);
        }

        // ---- epilogue: p' = ex2(s*c - sh_row)*adj; denom; fp16 -> smem ----
#pragma unroll
        for (int nt = 0; nt < 2; nt++) {
            const float p00 = fexp16s(sacc[nt][0], sh0) * aj0[nt].x;
            const float p01 = fexp16s(sacc[nt][1], sh0) * aj0[nt].y;
            const float p10 = fexp16s(sacc[nt][2], sh1) * aj1[nt].x;
            const float p11 = fexp16s(sacc[nt][3], sh1) * aj1[nt].y;
            den0 += p00 + p01;
            den1 += p10 + p11;
            *(uint32_t*)(smem + (psHi0 - sb) + nt * 16) = cvt2h(p00, p01);
            *(uint32_t*)(smem + (psHi0 - sb) + 8 * 80 + nt * 16) = cvt2h(p10, p11);
        }
        BAR_PAIR(s + 1);     // pair barrier: P rows of this s-strip complete

        // ---- O += Ph * Vh  (warp: 16 rows x 128 cols) ----
        const uint32_t vB = vBuf[cur] + vFrag;
#pragma unroll
        for (int kk = 0; kk < 2; kk++) {
            const uint32_t ko = kk * 32;
            uint32_t aph[4];
            ldsm4(aph, aPhi + ko);
#pragma unroll
            for (int nt = 0; nt < 8; nt++) {
                uint32_t bv[4];
                ldsm4(bv, vB + nt * (16 * 80) + ko);
                mma16816(oacc[nt * 2], aph, bv + 0);
                mma16816(oacc[nt * 2 + 1], aph, bv + 2);
            }
        }
        __syncthreads();     // sync3: all reads of K(ch),V(ch),P done CTA-wide

        // ---- issue K(ch+2) + V(ch+2) -> buf[cur] (one group) ----
        {
            const int mn = mbase + ((ch + 2) & (NCH_H - 1)) * TM;
#pragma unroll
            for (int it = 0; it < 4; it++) {
                const int row = ldRowK + it * 8;
                CPA16(kBuf[cur] + row * 528 + ldC16K * 16, xhiB + (size_t)(mn + row) * DD + ldC16K * 8);
            }
#pragma unroll
            for (int it = 0; it < 4; it++) {
                const int row = ldRowV + it * 64;
                CPA16(vBuf[cur] + row * 80 + ldC16V * 16, xthiB + (size_t)row * NN + mn + ldC16V * 8);
            }
            CP_COMMIT();
        }
    }

    // ---- denom combine + write partials ----
    den0 += __shfl_xor_sync(0xFFFFFFFFu, den0, 1);
    den0 += __shfl_xor_sync(0xFFFFFFFFu, den0, 2);
    den1 += __shfl_xor_sync(0xFFFFFFFFu, den1, 1);
    den1 += __shfl_xor_sync(0xFFFFFFFFu, den1, 2);
    __syncthreads();
    if ((lane & 3) == 0) {
        atomicAdd(&den_sm[r0], den0);
        atomicAdd(&den_sm[r0 + 8], den1);
    }
    __syncthreads();
    if (tid < 64)
        g_den[(size_t)half * BN + (size_t)bb * NN + i0 + tid] = den_sm[tid];

    float* nR0 = g_part + (size_t)half * BN * DD +
                 ((size_t)bb * NN + i0 + r0) * DD + hs * 128 + (lane & 3) * 2;
    float* nR1 = nR0 + 8 * DD;
#pragma unroll
    for (int nt = 0; nt < 16; nt++) {
        *(float2*)(nR0 + nt * 8) = make_float2(oacc[nt][0], oacc[nt][1]);
        *(float2*)(nR1 + nt * 8) = make_float2(oacc[nt][2], oacc[nt][3]);
    }
}

// ---------------- final: combine halves, (Yh+Yl) @ Wh + b, leaky relu ----------------
// k-chunk 32 -> smem 108.8KB -> 2 CTAs/SM
#define YW_YHI 0u
#define YW_YLO 33792u
#define YW_W0  67584u
#define YW_W1  88064u
#define YW_DEN 108544u
#define SMEM_YW 108800u

__global__ void __launch_bounds__(256, 2) ywb_kernel(const float* __restrict__ bvec,
                                                     float* __restrict__ out) {
    extern __shared__ char smem[];
    const uint32_t sb = smem_u32(smem);
    const int tid = threadIdx.x;
    const int wid = tid >> 5, lane = tid & 31;
    const int s = wid >> 1, hs = wid & 1;
    const int lane7 = lane & 7, l34 = (lane >> 3) & 1, l4 = lane >> 4;
    const int R0 = blockIdx.x * 64;

    const uint32_t wOff[2] = {YW_W0, YW_W1};
    const int ldRow = tid >> 2, ldC16 = tid & 3;  // W: 256 rows x 4 chunks (64B data/row)

    // issue W chunk 0 (k 0..31)
#pragma unroll
    for (int it = 0; it < 4; it++) {
        const int row = ldRow + it * 64;
        CPA16(sb + YW_W0 + row * 80 + ldC16 * 16, g_wthi + (size_t)row * DD + ldC16 * 8);
    }
    CP_COMMIT();

    // denom combine: eps scaled consistently with the per-row shift
    float* invd_s = (float*)(smem + YW_DEN);
    if (tid < 64) {
        const float d = g_den[R0 + tid] + g_den[BN + R0 + tid];
        const float eps = 1e-10f * exp2f(-g_sh2[R0 + tid]);
        invd_s[tid] = 1.0f / (d + eps);
    }
    __syncthreads();

    // Y = (n0+n1)*invd, split to fp16 hi/lo in smem
#pragma unroll
    for (int it = 0; it < 16; it++) {
        const int idx = it * 256 + tid;
        const int row = idx >> 6, c4 = idx & 63;
        const size_t off = (size_t)(R0 + row) * DD + c4 * 4;
        const float4 v0 = *(const float4*)(g_part + off);
        const float4 v1 = *(const float4*)(g_part + (size_t)BN * DD + off);
        const float iv = invd_s[row];
        const float y0 = (v0.x + v1.x) * iv, y1 = (v0.y + v1.y) * iv;
        const float y2 = (v0.z + v1.z) * iv, y3 = (v0.w + v1.w) * iv;
        const uint32_t h0 = cvt2h(y0, y1), h1 = cvt2h(y2, y3);
        const float2 f0 = h2f2(h0), f1 = h2f2(h1);
        const uint32_t l0 = cvt2h(y0 - f0.x, y1 - f0.y);
        const uint32_t l1 = cvt2h(y2 - f1.x, y3 - f1.y);
        *(uint2*)(smem + YW_YHI + row * 528 + c4 * 8) = make_uint2(h0, h1);
        *(uint2*)(smem + YW_YLO + row * 528 + c4 * 8) = make_uint2(l0, l1);
    }

    const int aRow = s * 16 + lane7 + l34 * 8;
    const uint32_t aYhi = sb + YW_YHI + aRow * 528 + l4 * 16;
    const uint32_t aYlo = sb + YW_YLO + aRow * 528 + l4 * 16;
    const int wRow = hs * 128 + l4 * 8 + lane7;
    const uint32_t wFragBase = (uint32_t)(wRow * 80 + l34 * 16);

    float oacc[16][4];
#pragma unroll
    for (int i = 0; i < 16; i++)
#pragma unroll
        for (int j = 0; j < 4; j++) oacc[i][j] = 0.f;

    for (int kc = 0; kc < 8; kc++) {
        if (kc < 7) {
            const uint32_t wb = wOff[(kc + 1) & 1];
#pragma unroll
            for (int it = 0; it < 4; it++) {
                const int row = ldRow + it * 64;
                CPA16(sb + wb + row * 80 + ldC16 * 16, g_wthi + (size_t)row * DD + (kc + 1) * 32 + ldC16 * 8);
            }
            CP_COMMIT();
            CP_WAIT(1);
        } else {
            CP_WAIT(0);
        }
        __syncthreads();

        const uint32_t bW = sb + wOff[kc & 1] + wFragBase;
#pragma unroll
        for (int kk = 0; kk < 2; kk++) {
            const uint32_t koA = (kc * 32 + kk * 16) * 2;
            const uint32_t koB = kk * 32;
            uint32_t ah[4], al[4];
            ldsm4(ah, aYhi + koA);
            ldsm4(al, aYlo + koA);
#pragma unroll
            for (int nt = 0; nt < 8; nt++) {
                uint32_t bh[4];
                ldsm4(bh, bW + nt * (16 * 80) + koB);
                mma16816(oacc[nt * 2], ah, bh + 0);
                mma16816(oacc[nt * 2 + 1], ah, bh + 2);
                mma16816(oacc[nt * 2], al, bh + 0);
                mma16816(oacc[nt * 2 + 1], al, bh + 2);
            }
        }
        __syncthreads();
    }

    const int r0 = s * 16 + (lane >> 2);
    const int c0 = hs * 128 + (lane & 3) * 2;
    float* oR0 = out + (size_t)(R0 + r0) * DD + c0;
    float* oR1 = oR0 + 8 * DD;
#pragma unroll
    for (int nt = 0; nt < 16; nt++) {
        const float2 bv = *(const float2*)(bvec + c0 + nt * 8);
        float v0 = oacc[nt][0] + bv.x, v1 = oacc[nt][1] + bv.y;
        float v2 = oacc[nt][2] + bv.x, v3 = oacc[nt][3] + bv.y;
        v0 = v0 > 0.f ? v0 : 0.01f * v0;
        v1 = v1 > 0.f ? v1 : 0.01f * v1;
        v2 = v2 > 0.f ? v2 : 0.01f * v2;
        v3 = v3 > 0.f ? v3 : 0.01f * v3;
        *(float2*)(oR0 + nt * 8) = make_float2(v0, v1);
        *(float2*)(oR1 + nt * 8) = make_float2(v2, v3);
    }
}

// ---------------------------------------------------------------------------
extern "C" void kernel_launch(void* const* d_in, const int* in_sizes, int n_in,
                              void* d_out, int out_size) {
    const float* inp = (const float*)d_in[0];
    const float* adj = (const float*)d_in[1];
    const float* W = (const float*)d_in[2];
    const float* b = (const float*)d_in[3];
    float* out = (float*)d_out;

    norm_kernel<<<BN / 8, 256>>>(inp);
    split_x_kernel<<<dim3(NN / 32, DD / 32, BB), dim3(32, 8)>>>(inp);
    split_wt_kernel<<<dim3(DD / 32, DD / 32), dim3(32, 8)>>>(W);

    cudaFuncSetAttribute(attn_kernel, cudaFuncAttributeMaxDynamicSharedMemorySize, SMEM_ATTN);
    attn_kernel<<<BB * 32 * 2, 256, SMEM_ATTN>>>(adj);

    cudaFuncSetAttribute(ywb_kernel, cudaFuncAttributeMaxDynamicSharedMemorySize, SMEM_YW);
    ywb_kernel<<<BN / 64, 256, SMEM_YW>>>(b, out);
}

// round 13
// speedup vs baseline: 1.0695x; 1.0695x over previous
#include <cuda_runtime.h>
#include <cuda_fp16.h>
#include <stdint.h>

#define BB 8
#define NN 2048
#define DD 256
#define BN (BB * NN)
#define TM 32
#define NCH_H 32

// ---------------- device scratch (allocation-free) ----------------
__device__ __half g_xhi[BN * DD];        // X row-major fp16
__device__ __half g_xthi[BB * DD * NN];  // X^T [b][k][m] fp16
__device__ __half g_wthi[DD * DD];       // W^T [n][k] fp16
__device__ __half g_p[(size_t)BN * NN];  // P' = shifted exp * adj, fp16
__device__ float g_part[2 * BN * DD];    // Y (normalized) lives in first BN*DD
__device__ float g_den[2 * BN];          // per-half denominators (scaled)
__device__ float g_sh2[BN];              // per-row exponent shift (log2 units)

// ---------------- helpers ----------------
__device__ __forceinline__ uint32_t smem_u32(const void* p) {
    uint32_t a;
    asm("{ .reg .u64 t; cvta.to.shared.u64 t, %1; cvt.u32.u64 %0, t; }" : "=r"(a) : "l"(p));
    return a;
}
__device__ __forceinline__ void ldsm4(uint32_t* r, uint32_t a) {
    asm volatile("ldmatrix.sync.aligned.m8n8.x4.shared.b16 {%0,%1,%2,%3}, [%4];"
                 : "=r"(r[0]), "=r"(r[1]), "=r"(r[2]), "=r"(r[3]) : "r"(a));
}
__device__ __forceinline__ void mma16816(float* c, const uint32_t* a, const uint32_t* b) {
    asm volatile("mma.sync.aligned.m16n8k16.row.col.f32.f16.f16.f32 "
                 "{%0,%1,%2,%3},{%4,%5,%6,%7},{%8,%9},{%0,%1,%2,%3};"
                 : "+f"(c[0]), "+f"(c[1]), "+f"(c[2]), "+f"(c[3])
                 : "r"(a[0]), "r"(a[1]), "r"(a[2]), "r"(a[3]), "r"(b[0]), "r"(b[1]));
}
#define CPA16(dst, src) \
    asm volatile("cp.async.cg.shared.global [%0], [%1], 16;" :: "r"(dst), "l"(src))
#define CP_COMMIT() asm volatile("cp.async.commit_group;")
#define CP_WAIT(n)  asm volatile("cp.async.wait_group %0;" :: "n"(n))

__device__ __forceinline__ uint32_t cvt2h(float lo, float hi) {
    uint32_t r;
    asm("cvt.rn.f16x2.f32 %0, %1, %2;" : "=r"(r) : "f"(hi), "f"(lo));
    return r;
}
__device__ __forceinline__ float2 h2f2(uint32_t u) {
    __half2 h = *(__half2*)&u;
    return __half22float2(h);
}
__device__ __forceinline__ float fexp16s(float s, float sh) {
    float r;
    asm("ex2.approx.f32 %0, %1;" : "=f"(r) : "f"(fmaf(s, 0.09016844005556021f, -sh)));
    return r;
}

// ---------------- preprocessing ----------------
__global__ void __launch_bounds__(256) norm_kernel(const float* __restrict__ inp) {
    const int row = blockIdx.x * 8 + (threadIdx.x >> 5);
    const int lane = threadIdx.x & 31;
    const float4* p = (const float4*)(inp + (size_t)row * DD);
    const float4 a = p[lane];
    const float4 b = p[lane + 32];
    float s = a.x * a.x + a.y * a.y + a.z * a.z + a.w * a.w +
              b.x * b.x + b.y * b.y + b.z * b.z + b.w * b.w;
#pragma unroll
    for (int o = 16; o > 0; o >>= 1) s += __shfl_xor_sync(0xFFFFFFFFu, s, o);
    if (lane == 0)
        g_sh2[row] = (s * 0.0625f - 8.0f) * 1.44269504f;
}

__global__ void __launch_bounds__(256) split_x_kernel(const float* __restrict__ inp) {
    __shared__ float t[32][33];
    const int b = blockIdx.z;
    const int m0 = blockIdx.x * 32, k0 = blockIdx.y * 32;
    const int tx = threadIdx.x, ty = threadIdx.y;
    const float* src = inp + ((size_t)b * NN + m0) * DD + k0;
#pragma unroll
    for (int s = 0; s < 4; s++) {
        const int m = ty + 8 * s;
        const float v = src[(size_t)m * DD + tx];
        t[m][tx] = v;
        g_xhi[((size_t)b * NN + m0 + m) * DD + k0 + tx] = __float2half_rn(v);
    }
    __syncthreads();
#pragma unroll
    for (int s = 0; s < 4; s++) {
        const int c = ty + 8 * s;
        g_xthi[((size_t)b * DD + k0 + c) * NN + m0 + tx] = __float2half_rn(t[tx][c]);
    }
}

__global__ void __launch_bounds__(256) split_wt_kernel(const float* __restrict__ W) {
    __shared__ float t[32][33];
    const int k0 = blockIdx.x * 32, n0 = blockIdx.y * 32;
    const int tx = threadIdx.x, ty = threadIdx.y;
#pragma unroll
    for (int s = 0; s < 4; s++) t[ty + 8 * s][tx] = W[(size_t)(k0 + ty + 8 * s) * DD + n0 + tx];
    __syncthreads();
#pragma unroll
    for (int s = 0; s < 4; s++) {
        const int k = ty + 8 * s;
        g_wthi[(size_t)(n0 + tx) * DD + k0 + k] = __float2half_rn(t[k][tx]);
    }
}

// ---------------- S kernel: P' = ex2(QK^T*c - sh)*adj -> gmem fp16; den ----------------
// Q fragments register-resident across the chunk loop.
#define SQ_Q   0u
#define SQ_K0  33792u
#define SQ_K1  50688u
#define SQ_DEN 67584u
#define SMEM_S 68096u

__global__ void __launch_bounds__(256, 2) s_kernel(const float* __restrict__ adj) {
    extern __shared__ char smem[];
    const uint32_t sb = smem_u32(smem);
    const int tid = threadIdx.x;
    const int wid = tid >> 5, lane = tid & 31;
    const int s = wid >> 1, hs = wid & 1;
    const int lane7 = lane & 7, l34 = (lane >> 3) & 1, l4 = lane >> 4;

    const int bb = blockIdx.x >> 6;
    const int i0 = ((blockIdx.x >> 1) & 31) * 64;
    const int half = blockIdx.x & 1;
    const int mbase = half * (NCH_H * TM);

    const __half* __restrict__ xhiB = g_xhi + (size_t)bb * NN * DD;
    const float* __restrict__ adjB = adj + (size_t)bb * NN * NN;
    __half* __restrict__ pB = g_p + ((size_t)bb * NN + i0) * NN;

    float* den_sm = (float*)(smem + SQ_DEN);
    if (tid < 64) den_sm[tid] = 0.f;

    const int ldRowK = tid >> 5, ldC16K = tid & 31;

    // Q (8 its), K0 (4 its), K1 (4 its) — 3 groups
#pragma unroll
    for (int it = 0; it < 8; it++) {
        const int row = ldRowK + it * 8;
        CPA16(sb + SQ_Q + row * 528 + ldC16K * 16, xhiB + (size_t)(i0 + row) * DD + ldC16K * 8);
    }
    CP_COMMIT();
#pragma unroll
    for (int it = 0; it < 4; it++) {
        const int row = ldRowK + it * 8;
        CPA16(sb + SQ_K0 + row * 528 + ldC16K * 16, xhiB + (size_t)(mbase + row) * DD + ldC16K * 8);
    }
    CP_COMMIT();
#pragma unroll
    for (int it = 0; it < 4; it++) {
        const int row = ldRowK + it * 8;
        CPA16(sb + SQ_K1 + row * 528 + ldC16K * 16, xhiB + (size_t)(mbase + TM + row) * DD + ldC16K * 8);
    }
    CP_COMMIT();

    CP_WAIT(2);          // Q ready
    __syncthreads();

    // hoist Q fragments into registers (64 regs)
    uint32_t qf[16][4];
    const uint32_t aQ = sb + SQ_Q + (uint32_t)(s * 16 + lane7 + l34 * 8) * 528 + l4 * 16;
#pragma unroll
    for (int kk = 0; kk < 16; kk++) ldsm4(qf[kk], aQ + kk * 32);

    const uint32_t kFrag = (uint32_t)((hs * 16 + l4 * 8 + lane7) * 528 + l34 * 16);
    const uint32_t kBuf[2] = {sb + SQ_K0, sb + SQ_K1};

    const int r0 = s * 16 + (lane >> 2);
    const int cb = hs * 16 + (lane & 3) * 2;
    const float sh0 = g_sh2[(size_t)bb * NN + i0 + r0];
    const float sh1 = g_sh2[(size_t)bb * NN + i0 + r0 + 8];
    float den0 = 0.f, den1 = 0.f;

    for (int ch = 0; ch < NCH_H; ch++) {
        const int m0 = mbase + ch * TM;
        const int cur = ch & 1;
        CP_WAIT(1);
        __syncthreads();

        // adj prefetch
        const float* adjR0 = adjB + (size_t)(i0 + r0) * NN + m0 + cb;
        const float* adjR1 = adjR0 + 8 * NN;
        float2 aj0[2], aj1[2];
#pragma unroll
        for (int nt = 0; nt < 2; nt++) {
            aj0[nt] = __ldg((const float2*)(adjR0 + nt * 8));
            aj1[nt] = __ldg((const float2*)(adjR1 + nt * 8));
        }

        // S = Q*K (Q from regs)
        const uint32_t kB = kBuf[cur] + kFrag;
        float sacc[2][4];
#pragma unroll
        for (int i = 0; i < 2; i++)
#pragma unroll
            for (int j = 0; j < 4; j++) sacc[i][j] = 0.f;
#pragma unroll
        for (int kk = 0; kk < 16; kk++) {
            uint32_t b0[4];
            ldsm4(b0, kB + kk * 32);
            mma16816(sacc[0], qf[kk], b0 + 0);
            mma16816(sacc[1], qf[kk], b0 + 2);
        }

        // epilogue: P' -> gmem fp16; denom
#pragma unroll
        for (int nt = 0; nt < 2; nt++) {
            const float p00 = fexp16s(sacc[nt][0], sh0) * aj0[nt].x;
            const float p01 = fexp16s(sacc[nt][1], sh0) * aj0[nt].y;
            const float p10 = fexp16s(sacc[nt][2], sh1) * aj1[nt].x;
            const float p11 = fexp16s(sacc[nt][3], sh1) * aj1[nt].y;
            den0 += p00 + p01;
            den1 += p10 + p11;
            *(uint32_t*)(pB + (size_t)r0 * NN + m0 + cb + nt * 8) = cvt2h(p00, p01);
            *(uint32_t*)(pB + (size_t)(r0 + 8) * NN + m0 + cb + nt * 8) = cvt2h(p10, p11);
        }
        __syncthreads();   // all warps done reading K(ch)

        // issue K(ch+2)
        {
            const int mn = mbase + ((ch + 2) & (NCH_H - 1)) * TM;
#pragma unroll
            for (int it = 0; it < 4; it++) {
                const int row = ldRowK + it * 8;
                CPA16(kBuf[cur] + row * 528 + ldC16K * 16, xhiB + (size_t)(mn + row) * DD + ldC16K * 8);
            }
            CP_COMMIT();
        }
    }

    // denominators
    den0 += __shfl_xor_sync(0xFFFFFFFFu, den0, 1);
    den0 += __shfl_xor_sync(0xFFFFFFFFu, den0, 2);
    den1 += __shfl_xor_sync(0xFFFFFFFFu, den1, 1);
    den1 += __shfl_xor_sync(0xFFFFFFFFu, den1, 2);
    __syncthreads();
    if ((lane & 3) == 0) {
        atomicAdd(&den_sm[r0], den0);
        atomicAdd(&den_sm[r0 + 8], den1);
    }
    __syncthreads();
    if (tid < 64)
        g_den[(size_t)half * BN + (size_t)bb * NN + i0 + tid] = den_sm[tid];
}

// ---------------- PV kernel: Y = (P' @ X) / den  (k = 2048, single wave) ----------------
#define PV_V0  0u
#define PV_V1  20480u
#define PV_P0  40960u
#define PV_P1  46080u
#define PV_DEN 51200u
#define SMEM_PV 51456u

__global__ void __launch_bounds__(256, 2) pv_kernel() {
    extern __shared__ char smem[];
    const uint32_t sb = smem_u32(smem);
    const int tid = threadIdx.x;
    const int wid = tid >> 5, lane = tid & 31;
    const int rs = wid >> 2, cs = wid & 3;   // 2 row-strips x 4 col-strips
    const int lane7 = lane & 7, l34 = (lane >> 3) & 1, l4 = lane >> 4;

    const int bb = blockIdx.x >> 5;
    const int i0 = (blockIdx.x & 31) * 64;

    const __half* __restrict__ xthiB = g_xthi + (size_t)bb * DD * NN;
    const __half* __restrict__ pB = g_p + ((size_t)bb * NN + i0) * NN;

    const int ldRowV = tid >> 2, ldC16V = tid & 3;  // V: rows 0..63 (+64*it), 4 chunks
    const int ldRowP = tid >> 2, ldC16P = tid & 3;  // P: 64 rows x 4 chunks

    // G0: V(0), P(0)
#pragma unroll
    for (int it = 0; it < 4; it++) {
        const int row = ldRowV + it * 64;
        CPA16(sb + PV_V0 + row * 80 + ldC16V * 16, xthiB + (size_t)row * NN + ldC16V * 8);
    }
    CPA16(sb + PV_P0 + ldRowP * 80 + ldC16P * 16, pB + (size_t)ldRowP * NN + ldC16P * 8);
    CP_COMMIT();
    // G1: V(1), P(1)
#pragma unroll
    for (int it = 0; it < 4; it++) {
        const int row = ldRowV + it * 64;
        CPA16(sb + PV_V1 + row * 80 + ldC16V * 16, xthiB + (size_t)row * NN + TM + ldC16V * 8);
    }
    CPA16(sb + PV_P1 + ldRowP * 80 + ldC16P * 16, pB + (size_t)ldRowP * NN + TM + ldC16P * 8);
    CP_COMMIT();

    // denom staging (read both halves, fold eps)
    float* invd_s = (float*)(smem + PV_DEN);
    if (tid < 64) {
        const size_t gi = (size_t)bb * NN + i0 + tid;
        const float d = g_den[gi] + g_den[BN + gi];
        const float eps = 1e-10f * exp2f(-g_sh2[gi]);
        invd_s[tid] = 1.0f / (d + eps);
    }

    const uint32_t pFrag = (uint32_t)((rs * 32 + lane7 + l34 * 8) * 80 + l4 * 16);
    const uint32_t vFrag = (uint32_t)((cs * 64 + l4 * 8 + lane7) * 80 + l34 * 16);
    const uint32_t pBuf[2] = {sb + PV_P0, sb + PV_P1};
    const uint32_t vBuf[2] = {sb + PV_V0, sb + PV_V1};

    float oacc[16][4];
#pragma unroll
    for (int i = 0; i < 16; i++)
#pragma unroll
        for (int j = 0; j < 4; j++) oacc[i][j] = 0.f;

    for (int ch = 0; ch < 64; ch++) {
        const int cur = ch & 1;
        CP_WAIT(1);
        __syncthreads();

        const uint32_t pA = pBuf[cur] + pFrag;
        const uint32_t vB = vBuf[cur] + vFrag;
#pragma unroll
        for (int kk = 0; kk < 2; kk++) {
            const uint32_t ko = kk * 32;
            uint32_t a0[4], a1[4];
            ldsm4(a0, pA + ko);
            ldsm4(a1, pA + 16 * 80 + ko);
#pragma unroll
            for (int j = 0; j < 4; j++) {
                uint32_t bv[4];
                ldsm4(bv, vB + j * (16 * 80) + ko);
                mma16816(oacc[j * 2 + 0], a0, bv + 0);
                mma16816(oacc[j * 2 + 1], a0, bv + 2);
                mma16816(oacc[8 + j * 2 + 0], a1, bv + 0);
                mma16816(oacc[8 + j * 2 + 1], a1, bv + 2);
            }
        }
        __syncthreads();   // reads of buf[cur] done

        // issue (V,P)(ch+2) -> buf[cur]
        {
            const int mn = ((ch + 2) & 63) * TM;
#pragma unroll
            for (int it = 0; it < 4; it++) {
                const int row = ldRowV + it * 64;
                CPA16(vBuf[cur] + row * 80 + ldC16V * 16, xthiB + (size_t)row * NN + mn + ldC16V * 8);
            }
            CPA16(pBuf[cur] + ldRowP * 80 + ldC16P * 16, pB + (size_t)ldRowP * NN + mn + ldC16P * 8);
            CP_COMMIT();
        }
    }

    // epilogue: normalize, write Y (f32) to g_part
    float* yB = g_part + ((size_t)bb * NN + i0) * DD;
#pragma unroll
    for (int t = 0; t < 2; t++) {
        const int rloc = rs * 32 + t * 16 + (lane >> 2);
        const float iv0 = invd_s[rloc];
        const float iv1 = invd_s[rloc + 8];
#pragma unroll
        for (int j = 0; j < 4; j++) {
#pragma unroll
            for (int nn = 0; nn < 2; nn++) {
                const int idx = t * 8 + j * 2 + nn;
                const int col = cs * 64 + j * 16 + nn * 8 + (lane & 3) * 2;
                *(float2*)(yB + (size_t)rloc * DD + col) =
                    make_float2(oacc[idx][0] * iv0, oacc[idx][1] * iv0);
                *(float2*)(yB + (size_t)(rloc + 8) * DD + col) =
                    make_float2(oacc[idx][2] * iv1, oacc[idx][3] * iv1);
            }
        }
    }
}

// ---------------- final: out = leaky_relu(Y @ W + b) ----------------
#define YW_YHI 0u
#define YW_YLO 33792u
#define YW_W0  67584u
#define YW_W1  88064u
#define SMEM_YW 108544u

__global__ void __launch_bounds__(256, 2) ywb_kernel(const float* __restrict__ bvec,
                                                     float* __restrict__ out) {
    extern __shared__ char smem[];
    const uint32_t sb = smem_u32(smem);
    const int tid = threadIdx.x;
    const int wid = tid >> 5, lane = tid & 31;
    const int s = wid >> 1, hs = wid & 1;
    const int lane7 = lane & 7, l34 = (lane >> 3) & 1, l4 = lane >> 4;
    const int R0 = blockIdx.x * 64;

    const uint32_t wOff[2] = {YW_W0, YW_W1};
    const int ldRow = tid >> 2, ldC16 = tid & 3;

    // issue W chunk 0 (k 0..31)
#pragma unroll
    for (int it = 0; it < 4; it++) {
        const int row = ldRow + it * 64;
        CPA16(sb + YW_W0 + row * 80 + ldC16 * 16, g_wthi + (size_t)row * DD + ldC16 * 8);
    }
    CP_COMMIT();

    // Y load + fp16 hi/lo split to smem
#pragma unroll
    for (int it = 0; it < 16; it++) {
        const int idx = it * 256 + tid;
        const int row = idx >> 6, c4 = idx & 63;
        const float4 v = *(const float4*)(g_part + (size_t)(R0 + row) * DD + c4 * 4);
        const uint32_t h0 = cvt2h(v.x, v.y), h1 = cvt2h(v.z, v.w);
        const float2 f0 = h2f2(h0), f1 = h2f2(h1);
        const uint32_t l0 = cvt2h(v.x - f0.x, v.y - f0.y);
        const uint32_t l1 = cvt2h(v.z - f1.x, v.w - f1.y);
        *(uint2*)(smem + YW_YHI + row * 528 + c4 * 8) = make_uint2(h0, h1);
        *(uint2*)(smem + YW_YLO + row * 528 + c4 * 8) = make_uint2(l0, l1);
    }

    const int aRow = s * 16 + lane7 + l34 * 8;
    const uint32_t aYhi = sb + YW_YHI + aRow * 528 + l4 * 16;
    const uint32_t aYlo = sb + YW_YLO + aRow * 528 + l4 * 16;
    const int wRow = hs * 128 + l4 * 8 + lane7;
    const uint32_t wFragBase = (uint32_t)(wRow * 80 + l34 * 16);

    float oacc[16][4];
#pragma unroll
    for (int i = 0; i < 16; i++)
#pragma unroll
        for (int j = 0; j < 4; j++) oacc[i][j] = 0.f;

    for (int kc = 0; kc < 8; kc++) {
        if (kc < 7) {
            const uint32_t wb = wOff[(kc + 1) & 1];
#pragma unroll
            for (int it = 0; it < 4; it++) {
                const int row = ldRow + it * 64;
                CPA16(sb + wb + row * 80 + ldC16 * 16, g_wthi + (size_t)row * DD + (kc + 1) * 32 + ldC16 * 8);
            }
            CP_COMMIT();
            CP_WAIT(1);
        } else {
            CP_WAIT(0);
        }
        __syncthreads();

        const uint32_t bW = sb + wOff[kc & 1] + wFragBase;
#pragma unroll
        for (int kk = 0; kk < 2; kk++) {
            const uint32_t koA = (kc * 32 + kk * 16) * 2;
            const uint32_t koB = kk * 32;
            uint32_t ah[4], al[4];
            ldsm4(ah, aYhi + koA);
            ldsm4(al, aYlo + koA);
#pragma unroll
            for (int nt = 0; nt < 8; nt++) {
                uint32_t bh[4];
                ldsm4(bh, bW + nt * (16 * 80) + koB);
                mma16816(oacc[nt * 2], ah, bh + 0);
                mma16816(oacc[nt * 2 + 1], ah, bh + 2);
                mma16816(oacc[nt * 2], al, bh + 0);
                mma16816(oacc[nt * 2 + 1], al, bh + 2);
            }
        }
        __syncthreads();
    }

    const int r0 = s * 16 + (lane >> 2);
    const int c0 = hs * 128 + (lane & 3) * 2;
    float* oR0 = out + (size_t)(R0 + r0) * DD + c0;
    float* oR1 = oR0 + 8 * DD;
#pragma unroll
    for (int nt = 0; nt < 16; nt++) {
        const float2 bv = *(const float2*)(bvec + c0 + nt * 8);
        float v0 = oacc[nt][0] + bv.x, v1 = oacc[nt][1] + bv.y;
        float v2 = oacc[nt][2] + bv.x, v3 = oacc[nt][3] + bv.y;
        v0 = v0 > 0.f ? v0 : 0.01f * v0;
        v1 = v1 > 0.f ? v1 : 0.01f * v1;
        v2 = v2 > 0.f ? v2 : 0.01f * v2;
        v3 = v3 > 0.f ? v3 : 0.01f * v3;
        *(float2*)(oR0 + nt * 8) = make_float2(v0, v1);
        *(float2*)(oR1 + nt * 8) = make_float2(v2, v3);
    }
}

// ---------------------------------------------------------------------------
extern "C" void kernel_launch(void* const* d_in, const int* in_sizes, int n_in,
                              void* d_out, int out_size) {
    const float* inp = (const float*)d_in[0];
    const float* adj = (const float*)d_in[1];
    const float* W = (const float*)d_in[2];
    const float* b = (const float*)d_in[3];
    float* out = (float*)d_out;

    norm_kernel<<<BN / 8, 256>>>(inp);
    split_x_kernel<<<dim3(NN / 32, DD / 32, BB), dim3(32, 8)>>>(inp);
    split_wt_kernel<<<dim3(DD / 32, DD / 32), dim3(32, 8)>>>(W);

    cudaFuncSetAttribute(s_kernel, cudaFuncAttributeMaxDynamicSharedMemorySize, SMEM_S);
    s_kernel<<<BB * 32 * 2, 256, SMEM_S>>>(adj);

    cudaFuncSetAttribute(pv_kernel, cudaFuncAttributeMaxDynamicSharedMemorySize, SMEM_PV);
    pv_kernel<<<BB * 32, 256, SMEM_PV>>>();

    cudaFuncSetAttribute(ywb_kernel, cudaFuncAttributeMaxDynamicSharedMemorySize, SMEM_YW);
    ywb_kernel<<<BN / 64, 256, SMEM_YW>>>(b, out);
}